// round 1
// baseline (speedup 1.0000x reference)
#include <cuda_runtime.h>

#define N_NODE 50000
#define N_EDGE 600000
#define D 128
#define NREL 3
#define SCAN_CHUNK 4096
#define NCHUNK ((N_NODE + SCAN_CHUNK - 1) / SCAN_CHUNK)   // 13

// ---------------- device scratch (static, no allocs) ----------------
__device__ int   g_deg   [NREL][N_NODE];
__device__ int   g_incl  [NREL][N_NODE];
__device__ int   g_offs  [NREL][N_NODE + 1];
__device__ int   g_cursor[NREL][N_NODE];
__device__ int   g_bsum  [NREL][NCHUNK];
__device__ int   g_boff  [NREL][NCHUNK];
__device__ int   g_sorted[NREL][N_EDGE];
__device__ float g_mean  [NREL][(size_t)N_NODE * D];   // 76.8 MB

// ---------------- phase 0: zero degrees ----------------
__global__ void zero_deg_kernel() {
    int i = blockIdx.x * blockDim.x + threadIdx.x;
    if (i < NREL * N_NODE) ((int*)g_deg)[i] = 0;
}

// ---------------- phase 1: count degrees ----------------
__global__ void count_kernel(const int* __restrict__ e0,
                             const int* __restrict__ e1,
                             const int* __restrict__ e2) {
    int i = blockIdx.x * blockDim.x + threadIdx.x;
    if (i >= NREL * N_EDGE) return;
    int r = i / N_EDGE;
    int e = i - r * N_EDGE;
    const int* ei = (r == 0) ? e0 : (r == 1) ? e1 : e2;
    int dst = ei[N_EDGE + e];          // row 1 = dst
    atomicAdd(&g_deg[r][dst], 1);
}

// ---------------- phase 2a: per-chunk inclusive scan ----------------
__global__ void scan1_kernel() {
    int r = blockIdx.y;
    int base = blockIdx.x * SCAN_CHUNK + threadIdx.x * 4;
    int v[4];
#pragma unroll
    for (int u = 0; u < 4; u++) {
        int idx = base + u;
        v[u] = (idx < N_NODE) ? g_deg[r][idx] : 0;
    }
    int t = v[0] + v[1] + v[2] + v[3];

    __shared__ int ws[32];
    int lane = threadIdx.x & 31;
    int wid  = threadIdx.x >> 5;
    int s = t;
#pragma unroll
    for (int o = 1; o < 32; o <<= 1) {
        int n = __shfl_up_sync(0xffffffffu, s, o);
        if (lane >= o) s += n;
    }
    if (lane == 31) ws[wid] = s;
    __syncthreads();
    if (wid == 0) {
        int x = ws[lane];
#pragma unroll
        for (int o = 1; o < 32; o <<= 1) {
            int n = __shfl_up_sync(0xffffffffu, x, o);
            if (lane >= o) x += n;
        }
        ws[lane] = x;
    }
    __syncthreads();
    int excl = s - t + (wid ? ws[wid - 1] : 0);
    int run = excl;
#pragma unroll
    for (int u = 0; u < 4; u++) {
        run += v[u];
        int idx = base + u;
        if (idx < N_NODE) g_incl[r][idx] = run;
    }
    if (threadIdx.x == 0) g_bsum[r][blockIdx.x] = ws[31];
}

// ---------------- phase 2b: scan chunk totals (tiny) ----------------
__global__ void scan2_kernel() {
    int r = threadIdx.x;
    if (r < NREL) {
        int run = 0;
        for (int c = 0; c < NCHUNK; c++) {
            g_boff[r][c] = run;
            run += g_bsum[r][c];
        }
    }
}

// ---------------- phase 2c: finalize offsets + cursors ----------------
__global__ void scan3_kernel() {
    int r = blockIdx.y;
    int boff = g_boff[r][blockIdx.x];
    int base = blockIdx.x * SCAN_CHUNK + threadIdx.x * 4;
#pragma unroll
    for (int u = 0; u < 4; u++) {
        int idx = base + u;
        if (idx < N_NODE) {
            int incl = g_incl[r][idx] + boff;
            g_offs[r][idx + 1] = incl;
            g_cursor[r][idx]   = incl - g_deg[r][idx];
        }
    }
    if (blockIdx.x == 0 && threadIdx.x == 0) g_offs[r][0] = 0;
}

// ---------------- phase 3: bucket src ids by dst ----------------
__global__ void bucket_kernel(const int* __restrict__ e0,
                              const int* __restrict__ e1,
                              const int* __restrict__ e2) {
    int i = blockIdx.x * blockDim.x + threadIdx.x;
    if (i >= NREL * N_EDGE) return;
    int r = i / N_EDGE;
    int e = i - r * N_EDGE;
    const int* ei = (r == 0) ? e0 : (r == 1) ? e1 : e2;
    int src = ei[e];
    int dst = ei[N_EDGE + e];
    int pos = atomicAdd(&g_cursor[r][dst], 1);
    g_sorted[r][pos] = src;
}

// ---------------- phase 4: per-node mean aggregation ----------------
// One warp per dst node. lane covers 4 feature columns -> float4 coalesced.
__global__ void aggregate_kernel(const float* __restrict__ xs, int r) {
    int warp = (blockIdx.x * blockDim.x + threadIdx.x) >> 5;
    int lane = threadIdx.x & 31;
    if (warp >= N_NODE) return;
    int beg = g_offs[r][warp];
    int end = g_offs[r][warp + 1];
    float ax = 0.f, ay = 0.f, az = 0.f, aw = 0.f;
    for (int e = beg; e < end; e++) {
        int s = g_sorted[r][e];
        float4 v = *(const float4*)&xs[(size_t)s * D + lane * 4];
        ax += v.x; ay += v.y; az += v.z; aw += v.w;
    }
    int deg = end - beg;
    float inv = (deg > 0) ? (1.0f / (float)deg) : 0.0f;
    float4 o = make_float4(ax * inv, ay * inv, az * inv, aw * inv);
    *(float4*)&g_mean[r][(size_t)warp * D + lane * 4] = o;
}

// ---------------- phase 5: fused GEMM ----------------
// out[m,d] = scale * ( sum_s A_s[m,:] . W_s[d,:]  + bias0[d] + bias1[d] )
// sources: s0 = g_mean[rM0] w/ W0 ; s1 = g_mean[rM1] w/ W1 (skipped if rM1<0);
//          s2 = X with (WXa + WXb) (WXb optional)
#define BM 128
#define BN 128
#define BK 8

__global__ void __launch_bounds__(256, 4)
gemm_kernel(int rM0, const float* __restrict__ W0,
            int rM1, const float* __restrict__ W1,
            const float* __restrict__ X,
            const float* __restrict__ WXa, const float* __restrict__ WXb,
            const float* __restrict__ bias0, const float* __restrict__ bias1,
            float scale, float* __restrict__ out) {
    __shared__ float As[BK][BM];
    __shared__ float Bs[BK][BN];

    int m0  = blockIdx.x * BM;
    int tid = threadIdx.x;
    int tx  = tid & 15;        // N direction, 16 * 8 = 128
    int ty  = tid >> 4;        // M direction, 16 * 8 = 128

    float acc[8][8];
#pragma unroll
    for (int i = 0; i < 8; i++)
#pragma unroll
        for (int j = 0; j < 8; j++) acc[i][j] = 0.f;

    int lrow = tid >> 1;            // 0..127 row for cooperative loads
    int lk4  = (tid & 1) * 4;       // 0 or 4

    for (int s = 0; s < 3; s++) {
        const float* A;
        const float* Wa;
        const float* Wb = nullptr;
        if (s == 0)      { A = g_mean[rM0]; Wa = W0; }
        else if (s == 1) { if (rM1 < 0) continue; A = g_mean[rM1]; Wa = W1; }
        else             { A = X; Wa = WXa; Wb = WXb; }

        for (int kk = 0; kk < D; kk += BK) {
            // load A tile: As[k][m] <- A[(m0+m)*D + kk + k]
            {
                int gm = m0 + lrow;
                float4 v = (gm < N_NODE)
                    ? *(const float4*)&A[(size_t)gm * D + kk + lk4]
                    : make_float4(0.f, 0.f, 0.f, 0.f);
                As[lk4 + 0][lrow] = v.x;
                As[lk4 + 1][lrow] = v.y;
                As[lk4 + 2][lrow] = v.z;
                As[lk4 + 3][lrow] = v.w;
            }
            // load B tile: Bs[k][d] <- Wa[d*D + kk + k] (+ Wb)
            {
                float4 v = *(const float4*)&Wa[(size_t)lrow * D + kk + lk4];
                if (Wb) {
                    float4 w = *(const float4*)&Wb[(size_t)lrow * D + kk + lk4];
                    v.x += w.x; v.y += w.y; v.z += w.z; v.w += w.w;
                }
                Bs[lk4 + 0][lrow] = v.x;
                Bs[lk4 + 1][lrow] = v.y;
                Bs[lk4 + 2][lrow] = v.z;
                Bs[lk4 + 3][lrow] = v.w;
            }
            __syncthreads();
#pragma unroll
            for (int k = 0; k < BK; k++) {
                float a[8], b[8];
                *(float4*)&a[0] = *(const float4*)&As[k][ty * 8];
                *(float4*)&a[4] = *(const float4*)&As[k][ty * 8 + 4];
                *(float4*)&b[0] = *(const float4*)&Bs[k][tx * 8];
                *(float4*)&b[4] = *(const float4*)&Bs[k][tx * 8 + 4];
#pragma unroll
                for (int i = 0; i < 8; i++)
#pragma unroll
                    for (int j = 0; j < 8; j++)
                        acc[i][j] += a[i] * b[j];
            }
            __syncthreads();
        }
    }

    // epilogue: bias + scale, vectorized stores
    float bsum[8];
#pragma unroll
    for (int j = 0; j < 8; j++) {
        float b = bias0[tx * 8 + j];
        if (bias1) b += bias1[tx * 8 + j];
        bsum[j] = b;
    }
#pragma unroll
    for (int i = 0; i < 8; i++) {
        int gm = m0 + ty * 8 + i;
        if (gm < N_NODE) {
            float4 o0, o1;
            o0.x = scale * (acc[i][0] + bsum[0]);
            o0.y = scale * (acc[i][1] + bsum[1]);
            o0.z = scale * (acc[i][2] + bsum[2]);
            o0.w = scale * (acc[i][3] + bsum[3]);
            o1.x = scale * (acc[i][4] + bsum[4]);
            o1.y = scale * (acc[i][5] + bsum[5]);
            o1.z = scale * (acc[i][6] + bsum[6]);
            o1.w = scale * (acc[i][7] + bsum[7]);
            *(float4*)&out[(size_t)gm * D + tx * 8]     = o0;
            *(float4*)&out[(size_t)gm * D + tx * 8 + 4] = o1;
        }
    }
}

// ---------------- launcher ----------------
extern "C" void kernel_launch(void* const* d_in, const int* in_sizes, int n_in,
                              void* d_out, int out_size) {
    const float* x_user   = (const float*)d_in[0];
    const float* x_item   = (const float*)d_in[1];
    const int*   ei_rates = (const int*)d_in[2];
    const int*   ei_rev   = (const int*)d_in[3];
    const int*   ei_fol   = (const int*)d_in[4];
    const float* Wl_rates = (const float*)d_in[5];
    const float* bl_rates = (const float*)d_in[6];
    const float* Wr_rates = (const float*)d_in[7];
    const float* Wl_rev   = (const float*)d_in[8];
    const float* bl_rev   = (const float*)d_in[9];
    const float* Wr_rev   = (const float*)d_in[10];
    const float* Wl_fol   = (const float*)d_in[11];
    const float* bl_fol   = (const float*)d_in[12];
    const float* Wr_fol   = (const float*)d_in[13];

    float* out_user = (float*)d_out;
    float* out_item = (float*)d_out + (size_t)N_NODE * D;

    // degree count
    zero_deg_kernel<<<(NREL * N_NODE + 255) / 256, 256>>>();
    count_kernel<<<(NREL * N_EDGE + 255) / 256, 256>>>(ei_rates, ei_rev, ei_fol);

    // prefix sums -> CSR offsets
    dim3 sg(NCHUNK, NREL);
    scan1_kernel<<<sg, 1024>>>();
    scan2_kernel<<<1, 32>>>();
    scan3_kernel<<<sg, 1024>>>();

    // bucket src ids by dst
    bucket_kernel<<<(NREL * N_EDGE + 255) / 256, 256>>>(ei_rates, ei_rev, ei_fol);

    // per-node mean aggregation (rel 0: src=user, rel 1: src=item, rel 2: src=user)
    int agg_blocks = (N_NODE * 32 + 255) / 256;
    aggregate_kernel<<<agg_blocks, 256>>>(x_user, 0);
    aggregate_kernel<<<agg_blocks, 256>>>(x_item, 1);
    aggregate_kernel<<<agg_blocks, 256>>>(x_user, 2);

    // fused output GEMMs
    int gemm_blocks = (N_NODE + BM - 1) / BM;   // 391
    // out_user = 0.5*(mean_rev@Wl_rev^T + mean_fol@Wl_fol^T + x_user@(Wr_rev+Wr_fol)^T + bl_rev + bl_fol)
    gemm_kernel<<<gemm_blocks, 256>>>(1, Wl_rev, 2, Wl_fol,
                                      x_user, Wr_rev, Wr_fol,
                                      bl_rev, bl_fol, 0.5f, out_user);
    // out_item = mean_rates@Wl_rates^T + x_item@Wr_rates^T + bl_rates
    gemm_kernel<<<gemm_blocks, 256>>>(0, Wl_rates, -1, nullptr,
                                      x_item, Wr_rates, nullptr,
                                      bl_rates, nullptr, 1.0f, out_item);
}

// round 2
// speedup vs baseline: 4.0439x; 4.0439x over previous
#include <cuda_runtime.h>

#define N_NODE 50000
#define N_EDGE 600000
#define D 128
#define NREL 3
#define SCAN_CHUNK 4096
#define NCHUNK ((N_NODE + SCAN_CHUNK - 1) / SCAN_CHUNK)   // 13

// ---------------- device scratch (static, no allocs) ----------------
__device__ int   g_deg   [NREL][N_NODE];
__device__ int   g_incl  [NREL][N_NODE];
__device__ int   g_offs  [NREL][N_NODE + 1];
__device__ int   g_cursor[NREL][N_NODE];
__device__ int   g_bsum  [NREL][NCHUNK];
__device__ int   g_boff  [NREL][NCHUNK];
__device__ int   g_sorted[NREL][N_EDGE];
__device__ float g_mean  [NREL][(size_t)N_NODE * D];   // 76.8 MB

// ---------------- phase 0: zero degrees ----------------
__global__ void zero_deg_kernel() {
    int i = blockIdx.x * blockDim.x + threadIdx.x;
    if (i < NREL * N_NODE) ((int*)g_deg)[i] = 0;
}

// ---------------- phase 1: count degrees ----------------
__global__ void count_kernel(const int* __restrict__ e0,
                             const int* __restrict__ e1,
                             const int* __restrict__ e2) {
    int i = blockIdx.x * blockDim.x + threadIdx.x;
    if (i >= NREL * N_EDGE) return;
    int r = i / N_EDGE;
    int e = i - r * N_EDGE;
    const int* ei = (r == 0) ? e0 : (r == 1) ? e1 : e2;
    int dst = ei[N_EDGE + e];          // row 1 = dst
    atomicAdd(&g_deg[r][dst], 1);
}

// ---------------- phase 2a: per-chunk inclusive scan ----------------
__global__ void scan1_kernel() {
    int r = blockIdx.y;
    int base = blockIdx.x * SCAN_CHUNK + threadIdx.x * 4;
    int v[4];
#pragma unroll
    for (int u = 0; u < 4; u++) {
        int idx = base + u;
        v[u] = (idx < N_NODE) ? g_deg[r][idx] : 0;
    }
    int t = v[0] + v[1] + v[2] + v[3];

    __shared__ int ws[32];
    int lane = threadIdx.x & 31;
    int wid  = threadIdx.x >> 5;
    int s = t;
#pragma unroll
    for (int o = 1; o < 32; o <<= 1) {
        int n = __shfl_up_sync(0xffffffffu, s, o);
        if (lane >= o) s += n;
    }
    if (lane == 31) ws[wid] = s;
    __syncthreads();
    if (wid == 0) {
        int x = ws[lane];
#pragma unroll
        for (int o = 1; o < 32; o <<= 1) {
            int n = __shfl_up_sync(0xffffffffu, x, o);
            if (lane >= o) x += n;
        }
        ws[lane] = x;
    }
    __syncthreads();
    int excl = s - t + (wid ? ws[wid - 1] : 0);
    int run = excl;
#pragma unroll
    for (int u = 0; u < 4; u++) {
        run += v[u];
        int idx = base + u;
        if (idx < N_NODE) g_incl[r][idx] = run;
    }
    if (threadIdx.x == 0) g_bsum[r][blockIdx.x] = ws[31];
}

// ---------------- phase 2b: scan chunk totals (tiny) ----------------
__global__ void scan2_kernel() {
    int r = threadIdx.x;
    if (r < NREL) {
        int run = 0;
        for (int c = 0; c < NCHUNK; c++) {
            g_boff[r][c] = run;
            run += g_bsum[r][c];
        }
    }
}

// ---------------- phase 2c: finalize offsets + cursors ----------------
__global__ void scan3_kernel() {
    int r = blockIdx.y;
    int boff = g_boff[r][blockIdx.x];
    int base = blockIdx.x * SCAN_CHUNK + threadIdx.x * 4;
#pragma unroll
    for (int u = 0; u < 4; u++) {
        int idx = base + u;
        if (idx < N_NODE) {
            int incl = g_incl[r][idx] + boff;
            g_offs[r][idx + 1] = incl;
            g_cursor[r][idx]   = incl - g_deg[r][idx];
        }
    }
    if (blockIdx.x == 0 && threadIdx.x == 0) g_offs[r][0] = 0;
}

// ---------------- phase 3: bucket src ids by dst ----------------
__global__ void bucket_kernel(const int* __restrict__ e0,
                              const int* __restrict__ e1,
                              const int* __restrict__ e2) {
    int i = blockIdx.x * blockDim.x + threadIdx.x;
    if (i >= NREL * N_EDGE) return;
    int r = i / N_EDGE;
    int e = i - r * N_EDGE;
    const int* ei = (r == 0) ? e0 : (r == 1) ? e1 : e2;
    int src = ei[e];
    int dst = ei[N_EDGE + e];
    int pos = atomicAdd(&g_cursor[r][dst], 1);
    g_sorted[r][pos] = src;
}

// ---------------- phase 4: fused per-node mean aggregation ----------------
// One warp per dst node, all 3 relations in one launch (grid.y = relation).
// Index loads are coalesced (one per lane per 32 edges) then broadcast via
// shfl; gathers unrolled x4 into 4 independent accumulators for MLP/ILP.
__global__ void aggregate_all_kernel(const float* __restrict__ xu,
                                     const float* __restrict__ xi) {
    int r = blockIdx.y;
    const float* __restrict__ xs = (r == 1) ? xi : xu;   // rel 1 gathers items
    int warp = (blockIdx.x * blockDim.x + threadIdx.x) >> 5;
    int lane = threadIdx.x & 31;
    if (warp >= N_NODE) return;
    int beg = g_offs[r][warp];
    int end = g_offs[r][warp + 1];

    float4 a0 = make_float4(0.f, 0.f, 0.f, 0.f);
    float4 a1 = a0, a2 = a0, a3 = a0;

    for (int e = beg; e < end; e += 32) {
        int n = end - e;
        if (n > 32) n = 32;
        int idx = (lane < n) ? g_sorted[r][e + lane] : 0;
        int j = 0;
        for (; j + 4 <= n; j += 4) {
            int s0 = __shfl_sync(0xffffffffu, idx, j + 0);
            int s1 = __shfl_sync(0xffffffffu, idx, j + 1);
            int s2 = __shfl_sync(0xffffffffu, idx, j + 2);
            int s3 = __shfl_sync(0xffffffffu, idx, j + 3);
            float4 v0 = __ldg((const float4*)(xs + (size_t)s0 * D) + lane);
            float4 v1 = __ldg((const float4*)(xs + (size_t)s1 * D) + lane);
            float4 v2 = __ldg((const float4*)(xs + (size_t)s2 * D) + lane);
            float4 v3 = __ldg((const float4*)(xs + (size_t)s3 * D) + lane);
            a0.x += v0.x; a0.y += v0.y; a0.z += v0.z; a0.w += v0.w;
            a1.x += v1.x; a1.y += v1.y; a1.z += v1.z; a1.w += v1.w;
            a2.x += v2.x; a2.y += v2.y; a2.z += v2.z; a2.w += v2.w;
            a3.x += v3.x; a3.y += v3.y; a3.z += v3.z; a3.w += v3.w;
        }
        for (; j < n; j++) {
            int s0 = __shfl_sync(0xffffffffu, idx, j);
            float4 v0 = __ldg((const float4*)(xs + (size_t)s0 * D) + lane);
            a0.x += v0.x; a0.y += v0.y; a0.z += v0.z; a0.w += v0.w;
        }
    }

    int deg = end - beg;
    float inv = (deg > 0) ? (1.0f / (float)deg) : 0.0f;
    float4 o;
    o.x = (a0.x + a1.x + a2.x + a3.x) * inv;
    o.y = (a0.y + a1.y + a2.y + a3.y) * inv;
    o.z = (a0.z + a1.z + a2.z + a3.z) * inv;
    o.w = (a0.w + a1.w + a2.w + a3.w) * inv;
    *(float4*)&g_mean[r][(size_t)warp * D + lane * 4] = o;
}

// ---------------- phase 5: fused GEMM (f32x2 packed FMA + reg prefetch) ----
// out[m,d] = scale * ( sum_s A_s[m,:] . W_s[d,:]  + bias0[d] (+ bias1[d]) )
// Source s: A = g_mean[ar[s]] if ar[s]>=0 else external pointer ap[s].
// wb (optional) is added to the LAST source's W at smem-load time.
#define BM 128
#define BN 128
#define BK 8

__global__ void __launch_bounds__(256, 2)
gemm_kernel(int nsrc,
            int a0r, const float* __restrict__ a0p, const float* __restrict__ w0,
            int a1r, const float* __restrict__ a1p, const float* __restrict__ w1,
            int a2r, const float* __restrict__ a2p, const float* __restrict__ w2,
            const float* __restrict__ wb,
            const float* __restrict__ bias0, const float* __restrict__ bias1,
            float scale, float* __restrict__ out) {
    __shared__ float As[BK][BM];
    __shared__ float Bs[BK][BN];

    int m0  = blockIdx.x * BM;
    int tid = threadIdx.x;
    int tx  = tid & 15;        // N direction, 16 * 8 = 128
    int ty  = tid >> 4;        // M direction, 16 * 8 = 128
    int lrow = tid >> 1;       // 0..127 row for cooperative loads
    int lk4  = (tid & 1) * 4;  // 0 or 4

    const float* Aarr[3];
    Aarr[0] = (a0r >= 0) ? g_mean[a0r] : a0p;
    Aarr[1] = (a1r >= 0) ? g_mean[a1r] : a1p;
    Aarr[2] = (a2r >= 0) ? g_mean[a2r] : a2p;
    const float* Warr[3] = {w0, w1, w2};

    unsigned long long accp[8][4];
#pragma unroll
    for (int i = 0; i < 8; i++)
#pragma unroll
        for (int j = 0; j < 4; j++) accp[i][j] = 0ull;

    int T = nsrc * (D / BK);   // tiles across all sources

    auto LOAD = [&](int t, float4& avo, float4& bvo) {
        int s  = t >> 4;               // 16 tiles per source
        int kk = (t & 15) * BK;
        const float* A = Aarr[s];
        const float* W = Warr[s];
        int gm = m0 + lrow;
        avo = (gm < N_NODE)
            ? *(const float4*)&A[(size_t)gm * D + kk + lk4]
            : make_float4(0.f, 0.f, 0.f, 0.f);
        float4 b = *(const float4*)&W[(size_t)lrow * D + kk + lk4];
        if (wb && s == nsrc - 1) {
            float4 w = *(const float4*)&wb[(size_t)lrow * D + kk + lk4];
            b.x += w.x; b.y += w.y; b.z += w.z; b.w += w.w;
        }
        bvo = b;
    };

    float4 av, bv;
    LOAD(0, av, bv);

    for (int t = 0; t < T; t++) {
        As[lk4 + 0][lrow] = av.x;
        As[lk4 + 1][lrow] = av.y;
        As[lk4 + 2][lrow] = av.z;
        As[lk4 + 3][lrow] = av.w;
        Bs[lk4 + 0][lrow] = bv.x;
        Bs[lk4 + 1][lrow] = bv.y;
        Bs[lk4 + 2][lrow] = bv.z;
        Bs[lk4 + 3][lrow] = bv.w;
        __syncthreads();

        float4 av2 = make_float4(0.f, 0.f, 0.f, 0.f);
        float4 bv2 = av2;
        if (t + 1 < T) LOAD(t + 1, av2, bv2);

#pragma unroll
        for (int k = 0; k < BK; k++) {
            float a_[8];
            *(float4*)&a_[0] = *(const float4*)&As[k][ty * 8];
            *(float4*)&a_[4] = *(const float4*)&As[k][ty * 8 + 4];
            unsigned long long bp[4];
            bp[0] = *(const unsigned long long*)&Bs[k][tx * 8 + 0];
            bp[1] = *(const unsigned long long*)&Bs[k][tx * 8 + 2];
            bp[2] = *(const unsigned long long*)&Bs[k][tx * 8 + 4];
            bp[3] = *(const unsigned long long*)&Bs[k][tx * 8 + 6];
#pragma unroll
            for (int i = 0; i < 8; i++) {
                unsigned long long ap;
                asm("mov.b64 %0, {%1, %1};" : "=l"(ap) : "f"(a_[i]));
#pragma unroll
                for (int j = 0; j < 4; j++)
                    asm("fma.rn.f32x2 %0, %1, %2, %0;"
                        : "+l"(accp[i][j]) : "l"(ap), "l"(bp[j]));
            }
        }
        __syncthreads();
        av = av2; bv = bv2;
    }

    // epilogue: unpack, bias + scale, vectorized stores
    float bsum[8];
#pragma unroll
    for (int j = 0; j < 8; j++) {
        float b = bias0[tx * 8 + j];
        if (bias1) b += bias1[tx * 8 + j];
        bsum[j] = b;
    }
#pragma unroll
    for (int i = 0; i < 8; i++) {
        int gm = m0 + ty * 8 + i;
        if (gm < N_NODE) {
            float o[8];
#pragma unroll
            for (int j = 0; j < 4; j++) {
                float lo, hi;
                asm("mov.b64 {%0, %1}, %2;" : "=f"(lo), "=f"(hi) : "l"(accp[i][j]));
                o[2 * j]     = lo;
                o[2 * j + 1] = hi;
            }
            float4 o0, o1;
            o0.x = scale * (o[0] + bsum[0]);
            o0.y = scale * (o[1] + bsum[1]);
            o0.z = scale * (o[2] + bsum[2]);
            o0.w = scale * (o[3] + bsum[3]);
            o1.x = scale * (o[4] + bsum[4]);
            o1.y = scale * (o[5] + bsum[5]);
            o1.z = scale * (o[6] + bsum[6]);
            o1.w = scale * (o[7] + bsum[7]);
            *(float4*)&out[(size_t)gm * D + tx * 8]     = o0;
            *(float4*)&out[(size_t)gm * D + tx * 8 + 4] = o1;
        }
    }
}

// ---------------- launcher ----------------
extern "C" void kernel_launch(void* const* d_in, const int* in_sizes, int n_in,
                              void* d_out, int out_size) {
    const float* x_user   = (const float*)d_in[0];
    const float* x_item   = (const float*)d_in[1];
    const int*   ei_rates = (const int*)d_in[2];
    const int*   ei_rev   = (const int*)d_in[3];
    const int*   ei_fol   = (const int*)d_in[4];
    const float* Wl_rates = (const float*)d_in[5];
    const float* bl_rates = (const float*)d_in[6];
    const float* Wr_rates = (const float*)d_in[7];
    const float* Wl_rev   = (const float*)d_in[8];
    const float* bl_rev   = (const float*)d_in[9];
    const float* Wr_rev   = (const float*)d_in[10];
    const float* Wl_fol   = (const float*)d_in[11];
    const float* bl_fol   = (const float*)d_in[12];
    const float* Wr_fol   = (const float*)d_in[13];

    float* out_user = (float*)d_out;
    float* out_item = (float*)d_out + (size_t)N_NODE * D;

    // degree count
    zero_deg_kernel<<<(NREL * N_NODE + 255) / 256, 256>>>();
    count_kernel<<<(NREL * N_EDGE + 255) / 256, 256>>>(ei_rates, ei_rev, ei_fol);

    // prefix sums -> CSR offsets
    dim3 sg(NCHUNK, NREL);
    scan1_kernel<<<sg, 1024>>>();
    scan2_kernel<<<1, 32>>>();
    scan3_kernel<<<sg, 1024>>>();

    // bucket src ids by dst
    bucket_kernel<<<(NREL * N_EDGE + 255) / 256, 256>>>(ei_rates, ei_rev, ei_fol);

    // fused per-node mean aggregation for all 3 relations
    dim3 ag((N_NODE * 32 + 255) / 256, NREL);
    aggregate_all_kernel<<<ag, 256>>>(x_user, x_item);

    // fused output GEMMs
    int gemm_blocks = (N_NODE + BM - 1) / BM;   // 391
    // out_user = 0.5*(mean_rev@Wl_rev^T + mean_fol@Wl_fol^T
    //                 + x_user@(Wr_rev+Wr_fol)^T + bl_rev + bl_fol)
    gemm_kernel<<<gemm_blocks, 256>>>(3,
                                      1, nullptr, Wl_rev,
                                      2, nullptr, Wl_fol,
                                      -1, x_user, Wr_rev,
                                      Wr_fol,
                                      bl_rev, bl_fol, 0.5f, out_user);
    // out_item = mean_rates@Wl_rates^T + x_item@Wr_rates^T + bl_rates
    gemm_kernel<<<gemm_blocks, 256>>>(2,
                                      0, nullptr, Wl_rates,
                                      -1, x_item, Wr_rates,
                                      -1, nullptr, nullptr,
                                      nullptr,
                                      bl_rates, nullptr, 1.0f, out_item);
}

// round 3
// speedup vs baseline: 4.4217x; 1.0934x over previous
#include <cuda_runtime.h>

#define N_NODE 50000
#define N_EDGE 600000
#define D 128
#define NREL 3
#define SCAN_CHUNK 4096
#define NCHUNK ((N_NODE + SCAN_CHUNK - 1) / SCAN_CHUNK)   // 13

// ---------------- device scratch (static, no allocs) ----------------
__device__ int   g_deg   [NREL][N_NODE];
__device__ int   g_incl  [NREL][N_NODE];
__device__ int   g_offs  [NREL][N_NODE + 1];
__device__ int   g_cursor[NREL][N_NODE];
__device__ int   g_bsum  [NREL][NCHUNK];
__device__ int   g_sorted[NREL][N_EDGE];
__device__ float g_mean  [NREL][(size_t)N_NODE * D];   // 76.8 MB

// ---------------- phase 0: zero degrees ----------------
__global__ void zero_deg_kernel() {
    int i = blockIdx.x * blockDim.x + threadIdx.x;
    if (i < NREL * N_NODE) ((int*)g_deg)[i] = 0;
}

// ---------------- phase 1: count degrees (4 edges / thread, int4) --------
__global__ void count_kernel(const int* __restrict__ e0,
                             const int* __restrict__ e1,
                             const int* __restrict__ e2) {
    int i = blockIdx.x * blockDim.x + threadIdx.x;       // quad index
    int nq = N_EDGE / 4;                                  // 150000
    if (i >= NREL * nq) return;
    int r = i / nq;
    int q = i - r * nq;
    const int* ei = (r == 0) ? e0 : (r == 1) ? e1 : e2;
    int4 dst = *(const int4*)&ei[N_EDGE + q * 4];
    atomicAdd(&g_deg[r][dst.x], 1);
    atomicAdd(&g_deg[r][dst.y], 1);
    atomicAdd(&g_deg[r][dst.z], 1);
    atomicAdd(&g_deg[r][dst.w], 1);
}

// ---------------- phase 2a: per-chunk inclusive scan ----------------
__global__ void scan1_kernel() {
    int r = blockIdx.y;
    int base = blockIdx.x * SCAN_CHUNK + threadIdx.x * 4;
    int v[4];
#pragma unroll
    for (int u = 0; u < 4; u++) {
        int idx = base + u;
        v[u] = (idx < N_NODE) ? g_deg[r][idx] : 0;
    }
    int t = v[0] + v[1] + v[2] + v[3];

    __shared__ int ws[32];
    int lane = threadIdx.x & 31;
    int wid  = threadIdx.x >> 5;
    int s = t;
#pragma unroll
    for (int o = 1; o < 32; o <<= 1) {
        int n = __shfl_up_sync(0xffffffffu, s, o);
        if (lane >= o) s += n;
    }
    if (lane == 31) ws[wid] = s;
    __syncthreads();
    if (wid == 0) {
        int x = ws[lane];
#pragma unroll
        for (int o = 1; o < 32; o <<= 1) {
            int n = __shfl_up_sync(0xffffffffu, x, o);
            if (lane >= o) x += n;
        }
        ws[lane] = x;
    }
    __syncthreads();
    int excl = s - t + (wid ? ws[wid - 1] : 0);
    int run = excl;
#pragma unroll
    for (int u = 0; u < 4; u++) {
        run += v[u];
        int idx = base + u;
        if (idx < N_NODE) g_incl[r][idx] = run;
    }
    if (threadIdx.x == 0) g_bsum[r][blockIdx.x] = ws[31];
}

// ---------------- phase 2b: finalize offsets + cursors (inline chunk scan) --
__global__ void scan3_kernel() {
    int r = blockIdx.y;
    int boff = 0;
#pragma unroll
    for (int c = 0; c < NCHUNK; c++)
        if (c < blockIdx.x) boff += g_bsum[r][c];
    int base = blockIdx.x * SCAN_CHUNK + threadIdx.x * 4;
#pragma unroll
    for (int u = 0; u < 4; u++) {
        int idx = base + u;
        if (idx < N_NODE) {
            int incl = g_incl[r][idx] + boff;
            g_offs[r][idx + 1] = incl;
            g_cursor[r][idx]   = incl - g_deg[r][idx];
        }
    }
    if (blockIdx.x == 0 && threadIdx.x == 0) g_offs[r][0] = 0;
}

// ---------------- phase 3: bucket src ids by dst (4 edges / thread) -------
__global__ void bucket_kernel(const int* __restrict__ e0,
                              const int* __restrict__ e1,
                              const int* __restrict__ e2) {
    int i = blockIdx.x * blockDim.x + threadIdx.x;
    int nq = N_EDGE / 4;
    if (i >= NREL * nq) return;
    int r = i / nq;
    int q = i - r * nq;
    const int* ei = (r == 0) ? e0 : (r == 1) ? e1 : e2;
    int4 src = *(const int4*)&ei[q * 4];
    int4 dst = *(const int4*)&ei[N_EDGE + q * 4];
    g_sorted[r][atomicAdd(&g_cursor[r][dst.x], 1)] = src.x;
    g_sorted[r][atomicAdd(&g_cursor[r][dst.y], 1)] = src.y;
    g_sorted[r][atomicAdd(&g_cursor[r][dst.z], 1)] = src.z;
    g_sorted[r][atomicAdd(&g_cursor[r][dst.w], 1)] = src.w;
}

// ---------------- phase 4: fused per-node mean aggregation ----------------
// One warp per dst node, all 3 relations in one launch (grid.y = relation).
__global__ void aggregate_all_kernel(const float* __restrict__ xu,
                                     const float* __restrict__ xi) {
    int r = blockIdx.y;
    const float* __restrict__ xs = (r == 1) ? xi : xu;   // rel 1 gathers items
    int warp = (blockIdx.x * blockDim.x + threadIdx.x) >> 5;
    int lane = threadIdx.x & 31;
    if (warp >= N_NODE) return;
    int beg = g_offs[r][warp];
    int end = g_offs[r][warp + 1];

    float4 a0 = make_float4(0.f, 0.f, 0.f, 0.f);
    float4 a1 = a0, a2 = a0, a3 = a0;

    for (int e = beg; e < end; e += 32) {
        int n = end - e;
        if (n > 32) n = 32;
        int idx = (lane < n) ? g_sorted[r][e + lane] : 0;
        int j = 0;
        for (; j + 4 <= n; j += 4) {
            int s0 = __shfl_sync(0xffffffffu, idx, j + 0);
            int s1 = __shfl_sync(0xffffffffu, idx, j + 1);
            int s2 = __shfl_sync(0xffffffffu, idx, j + 2);
            int s3 = __shfl_sync(0xffffffffu, idx, j + 3);
            float4 v0 = __ldg((const float4*)(xs + (size_t)s0 * D) + lane);
            float4 v1 = __ldg((const float4*)(xs + (size_t)s1 * D) + lane);
            float4 v2 = __ldg((const float4*)(xs + (size_t)s2 * D) + lane);
            float4 v3 = __ldg((const float4*)(xs + (size_t)s3 * D) + lane);
            a0.x += v0.x; a0.y += v0.y; a0.z += v0.z; a0.w += v0.w;
            a1.x += v1.x; a1.y += v1.y; a1.z += v1.z; a1.w += v1.w;
            a2.x += v2.x; a2.y += v2.y; a2.z += v2.z; a2.w += v2.w;
            a3.x += v3.x; a3.y += v3.y; a3.z += v3.z; a3.w += v3.w;
        }
        for (; j < n; j++) {
            int s0 = __shfl_sync(0xffffffffu, idx, j);
            float4 v0 = __ldg((const float4*)(xs + (size_t)s0 * D) + lane);
            a0.x += v0.x; a0.y += v0.y; a0.z += v0.z; a0.w += v0.w;
        }
    }

    int deg = end - beg;
    float inv = (deg > 0) ? (1.0f / (float)deg) : 0.0f;
    float4 o;
    o.x = (a0.x + a1.x + a2.x + a3.x) * inv;
    o.y = (a0.y + a1.y + a2.y + a3.y) * inv;
    o.z = (a0.z + a1.z + a2.z + a3.z) * inv;
    o.w = (a0.w + a1.w + a2.w + a3.w) * inv;
    *(float4*)&g_mean[r][(size_t)warp * D + lane * 4] = o;
}

// ---------------- phase 5: single fused GEMM for BOTH outputs -------------
// Blocks [0, NB_USER) compute out_user (3 sources, scale 0.5);
// blocks [NB_USER, NB_USER+NB_ITEM) compute out_item (2 sources, scale 1).
#define BM 128
#define BN 128
#define BK 8
#define NB (((N_NODE) + BM - 1) / BM)    // 391 per output

__global__ void __launch_bounds__(256, 2)
gemm_all_kernel(const float* __restrict__ x_user,
                const float* __restrict__ x_item,
                const float* __restrict__ Wl_rates, const float* __restrict__ bl_rates,
                const float* __restrict__ Wr_rates,
                const float* __restrict__ Wl_rev,   const float* __restrict__ bl_rev,
                const float* __restrict__ Wr_rev,
                const float* __restrict__ Wl_fol,   const float* __restrict__ bl_fol,
                const float* __restrict__ Wr_fol,
                float* __restrict__ out) {
    __shared__ float As[BK][BM];
    __shared__ float Bs[BK][BN];

    int out_id = (blockIdx.x >= NB) ? 1 : 0;
    int m0 = (blockIdx.x - out_id * NB) * BM;

    const float* Aarr[3];
    const float* Warr[3];
    const float* wb;
    const float* bias0;
    const float* bias1;
    float scale;
    int nsrc;
    float* outp;
    if (out_id == 0) {
        Aarr[0] = g_mean[1]; Warr[0] = Wl_rev;
        Aarr[1] = g_mean[2]; Warr[1] = Wl_fol;
        Aarr[2] = x_user;    Warr[2] = Wr_rev;  wb = Wr_fol;
        bias0 = bl_rev; bias1 = bl_fol; scale = 0.5f; nsrc = 3;
        outp = out;
    } else {
        Aarr[0] = g_mean[0]; Warr[0] = Wl_rates;
        Aarr[1] = x_item;    Warr[1] = Wr_rates; wb = nullptr;
        Aarr[2] = nullptr;   Warr[2] = nullptr;
        bias0 = bl_rates; bias1 = nullptr; scale = 1.0f; nsrc = 2;
        outp = out + (size_t)N_NODE * D;
    }

    int tid = threadIdx.x;
    int tx  = tid & 15;        // N direction, 16 * 8 = 128
    int ty  = tid >> 4;        // M direction, 16 * 8 = 128
    int lrow = tid >> 1;       // 0..127 row for cooperative loads
    int lk4  = (tid & 1) * 4;  // 0 or 4

    unsigned long long accp[8][4];
#pragma unroll
    for (int i = 0; i < 8; i++)
#pragma unroll
        for (int j = 0; j < 4; j++) accp[i][j] = 0ull;

    int T = nsrc * (D / BK);   // tiles across all sources

    auto LOAD = [&](int t, float4& avo, float4& bvo) {
        int s  = t >> 4;               // 16 k-tiles per source
        int kk = (t & 15) * BK;
        const float* A = Aarr[s];
        const float* W = Warr[s];
        int gm = m0 + lrow;
        avo = (gm < N_NODE)
            ? *(const float4*)&A[(size_t)gm * D + kk + lk4]
            : make_float4(0.f, 0.f, 0.f, 0.f);
        float4 b = *(const float4*)&W[(size_t)lrow * D + kk + lk4];
        if (wb && s == nsrc - 1) {
            float4 w = *(const float4*)&wb[(size_t)lrow * D + kk + lk4];
            b.x += w.x; b.y += w.y; b.z += w.z; b.w += w.w;
        }
        bvo = b;
    };

    float4 av, bv;
    LOAD(0, av, bv);

    for (int t = 0; t < T; t++) {
        As[lk4 + 0][lrow] = av.x;
        As[lk4 + 1][lrow] = av.y;
        As[lk4 + 2][lrow] = av.z;
        As[lk4 + 3][lrow] = av.w;
        Bs[lk4 + 0][lrow] = bv.x;
        Bs[lk4 + 1][lrow] = bv.y;
        Bs[lk4 + 2][lrow] = bv.z;
        Bs[lk4 + 3][lrow] = bv.w;
        __syncthreads();

        float4 av2 = make_float4(0.f, 0.f, 0.f, 0.f);
        float4 bv2 = av2;
        if (t + 1 < T) LOAD(t + 1, av2, bv2);

#pragma unroll
        for (int k = 0; k < BK; k++) {
            float a_[8];
            *(float4*)&a_[0] = *(const float4*)&As[k][ty * 8];
            *(float4*)&a_[4] = *(const float4*)&As[k][ty * 8 + 4];
            ulonglong2 q0 = *(const ulonglong2*)&Bs[k][tx * 8 + 0];
            ulonglong2 q1 = *(const ulonglong2*)&Bs[k][tx * 8 + 4];
            unsigned long long bp[4] = {q0.x, q0.y, q1.x, q1.y};
#pragma unroll
            for (int i = 0; i < 8; i++) {
                unsigned long long ap;
                asm("mov.b64 %0, {%1, %1};" : "=l"(ap) : "f"(a_[i]));
#pragma unroll
                for (int j = 0; j < 4; j++)
                    asm("fma.rn.f32x2 %0, %1, %2, %0;"
                        : "+l"(accp[i][j]) : "l"(ap), "l"(bp[j]));
            }
        }
        __syncthreads();
        av = av2; bv = bv2;
    }

    // epilogue: unpack, bias + scale, vectorized stores
    float bsum[8];
#pragma unroll
    for (int j = 0; j < 8; j++) {
        float b = bias0[tx * 8 + j];
        if (bias1) b += bias1[tx * 8 + j];
        bsum[j] = b;
    }
#pragma unroll
    for (int i = 0; i < 8; i++) {
        int gm = m0 + ty * 8 + i;
        if (gm < N_NODE) {
            float o[8];
#pragma unroll
            for (int j = 0; j < 4; j++) {
                float lo, hi;
                asm("mov.b64 {%0, %1}, %2;" : "=f"(lo), "=f"(hi) : "l"(accp[i][j]));
                o[2 * j]     = lo;
                o[2 * j + 1] = hi;
            }
            float4 o0, o1;
            o0.x = scale * (o[0] + bsum[0]);
            o0.y = scale * (o[1] + bsum[1]);
            o0.z = scale * (o[2] + bsum[2]);
            o0.w = scale * (o[3] + bsum[3]);
            o1.x = scale * (o[4] + bsum[4]);
            o1.y = scale * (o[5] + bsum[5]);
            o1.z = scale * (o[6] + bsum[6]);
            o1.w = scale * (o[7] + bsum[7]);
            *(float4*)&outp[(size_t)gm * D + tx * 8]     = o0;
            *(float4*)&outp[(size_t)gm * D + tx * 8 + 4] = o1;
        }
    }
}

// ---------------- launcher ----------------
extern "C" void kernel_launch(void* const* d_in, const int* in_sizes, int n_in,
                              void* d_out, int out_size) {
    const float* x_user   = (const float*)d_in[0];
    const float* x_item   = (const float*)d_in[1];
    const int*   ei_rates = (const int*)d_in[2];
    const int*   ei_rev   = (const int*)d_in[3];
    const int*   ei_fol   = (const int*)d_in[4];
    const float* Wl_rates = (const float*)d_in[5];
    const float* bl_rates = (const float*)d_in[6];
    const float* Wr_rates = (const float*)d_in[7];
    const float* Wl_rev   = (const float*)d_in[8];
    const float* bl_rev   = (const float*)d_in[9];
    const float* Wr_rev   = (const float*)d_in[10];
    const float* Wl_fol   = (const float*)d_in[11];
    const float* bl_fol   = (const float*)d_in[12];
    const float* Wr_fol   = (const float*)d_in[13];

    float* outp = (float*)d_out;

    int nq = NREL * (N_EDGE / 4);
    // launch 0: zero degrees
    zero_deg_kernel<<<(NREL * N_NODE + 255) / 256, 256>>>();
    // launch 1: degree count
    count_kernel<<<(nq + 255) / 256, 256>>>(ei_rates, ei_rev, ei_fol);
    // launches 2-3: prefix sums -> CSR offsets
    dim3 sg(NCHUNK, NREL);
    scan1_kernel<<<sg, 1024>>>();
    scan3_kernel<<<sg, 1024>>>();
    // launch 4: bucket src ids by dst
    bucket_kernel<<<(nq + 255) / 256, 256>>>(ei_rates, ei_rev, ei_fol);
    // launch 5: fused per-node mean aggregation (profiled by -s 5 -c 1)
    dim3 ag((N_NODE * 32 + 255) / 256, NREL);
    aggregate_all_kernel<<<ag, 256>>>(x_user, x_item);
    // launch 6: single fused GEMM for both outputs
    gemm_all_kernel<<<2 * NB, 256>>>(x_user, x_item,
                                     Wl_rates, bl_rates, Wr_rates,
                                     Wl_rev, bl_rev, Wr_rev,
                                     Wl_fol, bl_fol, Wr_fol,
                                     outp);
}